// round 9
// baseline (speedup 1.0000x reference)
#include <cuda_runtime.h>
#include <cuda.h>
#include <cstdint>

// ============================================================================
// PHM8Linear: out[131072,512] = X[131072,512] @ H[512,512]^T + bias
// H[a*64+b][c*64+d] = sum_i A[i,a,c] * S[i,b,d]
// tcgen05 TF32 SS GEMM, persistent grid=148.
// CTA pair {2c,2c+1} handles nb=0/1 of the same m-tile sequence (X L2 reuse).
// Sub-tile A (rows m0..+127, TMEM cols 0-255) and B (rows m0+128..+255,
// cols 256-511) staggered by 16 positions on ONE periodic H stream.
// Round 9: 6-stage x 32KB ring (KC=16, SW64 swizzle) for 2x TMA fill depth.
// warp0=dispatcher, warp1=producer, warps 2-7=epilogue.
// X raw fp32 (HW tf32 truncate); H pre-rounded RN in build_H.
// ============================================================================

#define N_F    512
#define KC     16          // K elems per chunk = 64 bytes = SW64 row
#define NSTAGE 6
#define GRID   148
#define NPAIR  74          // GRID/2 m-tile streams
#define M_TILES 512        // 131072/256
#define PPT    32          // positions per tile (512/KC)

__device__ float g_H[N_F * N_F];   // precomputed H (tf32-rounded fp32 bits)

#if defined(__CUDA_ARCH__) && (defined(__CUDA_ARCH_FEAT_SM103_ALL) || \
    defined(__CUDA_ARCH_FEAT_SM100_ALL) || defined(__CUDA_ARCH_FEAT_SM101_ALL))
#define HAS_TCGEN05 1
#else
#define HAS_TCGEN05 0
#endif

// ---------------- smem layout (dynamic), tcgen05 path ----------------
// Stage (32KB): X_A 8KB @+0 | X_B 8KB @+8192 | H 16KB @+16384
#define OFF_TPTR    0
#define OFF_FULL(s) (8 + 8 * (s))
#define OFF_DONE(s) (64 + 8 * (s))
#define OFF_EPI_A   128
#define OFF_EPI_B   136
#define OFF_DFREE_A 144
#define OFF_DFREE_B 152
#define OFF_STG(s)  (1024 + (s) * 32768)
#define SMEM_BYTES  (1024 + NSTAGE * 32768)

// idesc: kind::tf32, D=F32(1<<4), A=TF32(2<<7), B=TF32(2<<10), N=256, M=128
#define IDESC_TF32_N256 ((1u << 4) | (2u << 7) | (2u << 10) | ((256u / 8u) << 17) | ((128u / 16u) << 24))

// K-major SW64 smem descriptor base: layout=SW64(4), version=1, SBO=32, LBO=1
// (SW64 atom = 8 rows x 64B; SBO=32*16=512B = 8 rows; LBO=1*16=16B)
static __device__ __host__ constexpr uint64_t DESC_BASE_SW64 =
    (uint64_t(4) << 61) | (uint64_t(1) << 46) | (uint64_t(32) << 32) | (uint64_t(1) << 16);

__device__ __forceinline__ uint32_t s2u(const void* p) {
    uint32_t a;
    asm("{ .reg .u64 t; cvta.to.shared.u64 t, %1; cvt.u32.u64 %0, t; }" : "=r"(a) : "l"(p));
    return a;
}

#define MBAR_INIT(addr, cnt) \
    asm volatile("mbarrier.init.shared.b64 [%0], %1;" :: "r"(addr), "r"(cnt) : "memory")

#define MBAR_ARRIVE(addr) \
    asm volatile("mbarrier.arrive.shared.b64 _, [%0];" :: "r"(addr) : "memory")

#define MBAR_EXPECT_TX(addr, bytes) \
    asm volatile("mbarrier.arrive.expect_tx.shared.b64 _, [%0], %1;" :: "r"(addr), "r"(bytes) : "memory")

#define MBAR_WAIT(addr, parity) do {                                           \
    uint32_t _mb = (addr); uint32_t _ph = (parity); uint32_t _dn;              \
    asm volatile("{\n\t.reg .pred p;\n\t"                                      \
        "mbarrier.try_wait.parity.acquire.cta.shared::cta.b64 p, [%1], %2;\n\t"\
        "selp.b32 %0, 1, 0, p;\n\t}" : "=r"(_dn) : "r"(_mb), "r"(_ph) : "memory"); \
    while (!_dn) {                                                             \
        asm volatile("{\n\t.reg .pred p;\n\t"                                  \
            "mbarrier.try_wait.parity.acquire.cta.shared::cta.b64 p, [%1], %2, 0x989680;\n\t" \
            "selp.b32 %0, 1, 0, p;\n\t}" : "=r"(_dn) : "r"(_mb), "r"(_ph) : "memory"); \
    }                                                                          \
} while (0)

#define TMA2D(smem, map, cx, cy, mbar)                                         \
    asm volatile("cp.async.bulk.tensor.2d.shared::cta.global.tile.mbarrier::complete_tx::bytes " \
        "[%0], [%1, {%2, %3}], [%4];"                                          \
        :: "r"(smem), "l"(map), "r"(cx), "r"(cy), "r"(mbar) : "memory")

#define MMA_TF32(dst, adsc, bdsc, en)                                          \
    asm volatile("{\n\t.reg .pred p;\n\tsetp.ne.u32 p, %5, 0;\n\t"             \
        "tcgen05.mma.cta_group::1.kind::tf32 [%0], %1, %2, %3, {%4,%4,%4,%4}, p;\n\t}" \
        :: "r"(dst), "l"(adsc), "l"(bdsc), "r"(IDESC_TF32_N256), "r"(0u), "r"(en) : "memory")

#define TC_COMMIT(mbar)                                                        \
    asm volatile("tcgen05.commit.cta_group::1.mbarrier::arrive::one.shared::cluster.b64 [%0];" \
        :: "r"(mbar) : "memory")

// ---------------------------------------------------------------------------
// H precompute: H[r=a*64+b][k=c*64+d] = sum_i A[i,a,c]*S[i,b,d], RN->tf32
// ---------------------------------------------------------------------------
__global__ void build_H(const float* __restrict__ A, const float* __restrict__ S) {
    int r = blockIdx.x;     // 0..511
    int k = threadIdx.x;    // 0..511
    int a = r >> 6, bb = r & 63, c = k >> 6, d = k & 63;
    float acc = 0.f;
#pragma unroll
    for (int i = 0; i < 8; i++)
        acc = fmaf(A[i * 64 + a * 8 + c], S[i * 4096 + bb * 64 + d], acc);
    uint32_t t;
    asm("cvt.rna.tf32.f32 %0, %1;" : "=r"(t) : "f"(acc));
    g_H[r * N_F + k] = __uint_as_float(t);
}

// ---------------------------------------------------------------------------
// Main GEMM kernel
// ---------------------------------------------------------------------------
__global__ void __launch_bounds__(256, 1) phm_gemm(
    const float* __restrict__ x,
    const float* __restrict__ bias, float* __restrict__ out,
    int ntiles,
    const __grid_constant__ CUtensorMap mx,
    const __grid_constant__ CUtensorMap mh)
{
    int bid = blockIdx.x;

#if HAS_TCGEN05
    // =================== tcgen05 TF32 path (sm_103a) =====================
    (void)x; (void)ntiles;
    extern __shared__ char smem_raw[];
    uint32_t sb = s2u(smem_raw);
    int tid = threadIdx.x, wid = tid >> 5, lid = tid & 31;

    int c  = bid >> 1;          // m-tile stream (0..73)
    int nb = bid & 1;           // N half (fixed per CTA)
    int cnt = 1 + (M_TILES - 1 - c) / NPAIR;   // tiles for this stream
    int P = PPT * cnt + 16;                    // stream positions (tail for B)

    if (wid == 0) {
        asm volatile("tcgen05.alloc.cta_group::1.sync.aligned.shared::cta.b32 [%0], %1;"
                     :: "r"(sb + OFF_TPTR), "r"(512) : "memory");
        asm volatile("tcgen05.relinquish_alloc_permit.cta_group::1.sync.aligned;");
    }
    if (tid == 0) {
#pragma unroll
        for (int s = 0; s < NSTAGE; s++) {
            MBAR_INIT(sb + OFF_FULL(s), 1);
            MBAR_INIT(sb + OFF_DONE(s), 1);
        }
        MBAR_INIT(sb + OFF_EPI_A, 1);
        MBAR_INIT(sb + OFF_EPI_B, 1);
        MBAR_INIT(sb + OFF_DFREE_A, 6);
        MBAR_INIT(sb + OFF_DFREE_B, 6);
    }
    __syncthreads();
    uint32_t tmem;
    asm volatile("ld.shared.b32 %0, [%1];" : "=r"(tmem) : "r"(sb + OFF_TPTR));

    if (wid == 0 && lid == 0) {
        // ---------------- MMA dispatcher ----------------
        uint64_t dA[NSTAGE], dB[NSTAGE], dH[NSTAGE];
#pragma unroll
        for (int s = 0; s < NSTAGE; s++) {
            dA[s] = DESC_BASE_SW64 | (((sb + OFF_STG(s))         >> 4) & 0x3FFF);
            dB[s] = DESC_BASE_SW64 | (((sb + OFF_STG(s) + 8192)  >> 4) & 0x3FFF);
            dH[s] = DESC_BASE_SW64 | (((sb + OFF_STG(s) + 16384) >> 4) & 0x3FFF);
        }
        int cs = 0, ph = 0;
        for (int p = 0; p < P; p++) {
            int k  = p & (PPT - 1);
            int j  = p >> 5;
            int jB = (p - 16) >> 5;
            int aA = (j < cnt);
            int aB = (p >= 16) && (jB < cnt);

            MBAR_WAIT(sb + OFF_FULL(cs), ph);

            if (k == 0) {
                // B mid-window: feed the pipe before A's D-free wait
                if (aB) {
#pragma unroll
                    for (int ks = 0; ks < 2; ks++)
                        MMA_TF32(tmem + 256, dB[cs] + 2 * ks, dH[cs] + 2 * ks, 1u);
                }
                if (aA) {
                    if (j > 0) {
                        MBAR_WAIT(sb + OFF_DFREE_A, (j - 1) & 1);
                        asm volatile("tcgen05.fence::after_thread_sync;" ::: "memory");
                    }
#pragma unroll
                    for (int ks = 0; ks < 2; ks++)
                        MMA_TF32(tmem, dA[cs] + 2 * ks, dH[cs] + 2 * ks, ks ? 1u : 0u);
                }
            } else if (k == 16) {
                if (aA) {
#pragma unroll
                    for (int ks = 0; ks < 2; ks++)
                        MMA_TF32(tmem, dA[cs] + 2 * ks, dH[cs] + 2 * ks, 1u);
                }
                if (aB) {
                    if (jB > 0) {
                        MBAR_WAIT(sb + OFF_DFREE_B, (jB - 1) & 1);
                        asm volatile("tcgen05.fence::after_thread_sync;" ::: "memory");
                    }
#pragma unroll
                    for (int ks = 0; ks < 2; ks++)
                        MMA_TF32(tmem + 256, dB[cs] + 2 * ks, dH[cs] + 2 * ks, ks ? 1u : 0u);
                }
            } else {
                if (aA) {
#pragma unroll
                    for (int ks = 0; ks < 2; ks++)
                        MMA_TF32(tmem, dA[cs] + 2 * ks, dH[cs] + 2 * ks, 1u);
                }
                if (aB) {
#pragma unroll
                    for (int ks = 0; ks < 2; ks++)
                        MMA_TF32(tmem + 256, dB[cs] + 2 * ks, dH[cs] + 2 * ks, 1u);
                }
            }
            TC_COMMIT(sb + OFF_DONE(cs));
            if (aA && k == 31) TC_COMMIT(sb + OFF_EPI_A);
            if (aB && k == 15) TC_COMMIT(sb + OFF_EPI_B);
            if (++cs == NSTAGE) { cs = 0; ph ^= 1; }
        }
    } else if (wid == 1 && lid == 0) {
        // ---------------- TMA producer ----------------
        int cs = 0, ph = 0, filled = 0;
        for (int p = 0; p < P; p++) {
            int k  = p & (PPT - 1);
            int j  = p >> 5;
            int jB = (p - 16) >> 5;
            int aA = (j < cnt);
            int aB = (p >= 16) && (jB < cnt);

            if (filled >= NSTAGE)
                MBAR_WAIT(sb + OFF_DONE(cs), ph ^ 1);
            uint32_t bytes = 16384u + (aA ? 8192u : 0u) + (aB ? 8192u : 0u);
            MBAR_EXPECT_TX(sb + OFF_FULL(cs), bytes);
            if (aA)
                TMA2D(sb + OFF_STG(cs), &mx, k * KC,
                      (c + NPAIR * j) * 256, sb + OFF_FULL(cs));
            if (aB)
                TMA2D(sb + OFF_STG(cs) + 8192, &mx, k * KC,
                      (c + NPAIR * jB) * 256 + 128, sb + OFF_FULL(cs));
            TMA2D(sb + OFF_STG(cs) + 16384, &mh, k * KC, nb * 256, sb + OFF_FULL(cs));
            filled++;
            if (++cs == NSTAGE) { cs = 0; ph ^= 1; }
        }
    } else if (wid >= 2) {
        // ---------------- epilogue warps (2..7) ----------------
        // subpartition coverage: sp0=warp4, sp1=warp5, sp2=warps2/6, sp3=warps3/7
        int sp = wid & 3;
        int nch = (sp < 2) ? 8 : 4;
        int ch0 = (sp < 2) ? 0 : ((wid >= 6) ? 4 : 0);
        for (int j = 0; j < cnt; j++) {
#pragma unroll
            for (int half = 0; half < 2; half++) {   // 0 = A event, 1 = B event
                uint32_t epib = sb + (half ? OFF_EPI_B : OFF_EPI_A);
                uint32_t dfrb = sb + (half ? OFF_DFREE_B : OFF_DFREE_A);
                MBAR_WAIT(epib, j & 1);
                asm volatile("tcgen05.fence::after_thread_sync;" ::: "memory");

                size_t row = (size_t)((c + NPAIR * j) * 256 + half * 128 + sp * 32 + lid);
                float* orow = out + row * N_F + nb * 256;
                uint32_t tb = tmem + half * 256;
                for (int cc = 0; cc < nch; cc++) {
                    int c0 = (ch0 + cc) * 32;
                    uint32_t r[32];
                    asm volatile(
                        "tcgen05.ld.sync.aligned.32x32b.x32.b32 "
                        "{%0, %1, %2, %3, %4, %5, %6, %7, "
                        " %8, %9, %10, %11, %12, %13, %14, %15, "
                        " %16, %17, %18, %19, %20, %21, %22, %23, "
                        " %24, %25, %26, %27, %28, %29, %30, %31}, [%32];"
                        : "=r"(r[0]),  "=r"(r[1]),  "=r"(r[2]),  "=r"(r[3]),
                          "=r"(r[4]),  "=r"(r[5]),  "=r"(r[6]),  "=r"(r[7]),
                          "=r"(r[8]),  "=r"(r[9]),  "=r"(r[10]), "=r"(r[11]),
                          "=r"(r[12]), "=r"(r[13]), "=r"(r[14]), "=r"(r[15]),
                          "=r"(r[16]), "=r"(r[17]), "=r"(r[18]), "=r"(r[19]),
                          "=r"(r[20]), "=r"(r[21]), "=r"(r[22]), "=r"(r[23]),
                          "=r"(r[24]), "=r"(r[25]), "=r"(r[26]), "=r"(r[27]),
                          "=r"(r[28]), "=r"(r[29]), "=r"(r[30]), "=r"(r[31])
                        : "r"(tb + c0));
                    asm volatile("tcgen05.wait::ld.sync.aligned;" ::: "memory");
                    if (cc == nch - 1) {
                        // TMEM cols free (data in regs) -> release dispatcher early
                        asm volatile("tcgen05.fence::before_thread_sync;" ::: "memory");
                        if (lid == 0) MBAR_ARRIVE(dfrb);
                    }
#pragma unroll
                    for (int q = 0; q < 8; q++) {
                        float4 bv = *reinterpret_cast<const float4*>(bias + nb * 256 + c0 + q * 4);
                        float4 v;
                        v.x = __uint_as_float(r[q * 4 + 0]) + bv.x;
                        v.y = __uint_as_float(r[q * 4 + 1]) + bv.y;
                        v.z = __uint_as_float(r[q * 4 + 2]) + bv.z;
                        v.w = __uint_as_float(r[q * 4 + 3]) + bv.w;
                        *reinterpret_cast<float4*>(orow + c0 + q * 4) = v;
                    }
                }
            }
        }
    }

    __syncthreads();
    if (wid == 0) {
        asm volatile("tcgen05.dealloc.cta_group::1.sync.aligned.b32 %0, %1;"
                     :: "r"(tmem), "r"(512));
    }

#else
    // =================== SIMT fp32 fallback (non-'a' pass) ================
    (void)mx; (void)mh;
    extern __shared__ char smem_raw[];
    float* Xs = reinterpret_cast<float*>(smem_raw);          // [128][33]
    float* Hs = Xs + 128 * 33;                               // [64][33]

    int tid = threadIdx.x;
    int ty = tid >> 4, tx = tid & 15;

    for (int g = bid; g < ntiles; g += GRID) {
        int m0 = (g >> 1) * 256;
        int nb = g & 1;
        for (int half = 0; half < 2; half++) {
            int m0h = m0 + half * 128;
            for (int nc = 0; nc < 4; nc++) {
                int col0 = nb * 256 + nc * 64;
                float acc[8][4];
#pragma unroll
                for (int i = 0; i < 8; i++)
#pragma unroll
                    for (int j = 0; j < 4; j++) acc[i][j] = 0.f;

                for (int kb = 0; kb < 16; kb++) {
#pragma unroll
                    for (int it = 0; it < 16; it++) {
                        int idx = tid + it * 256;
                        int r = idx >> 5, k = idx & 31;
                        Xs[r * 33 + k] = x[(size_t)(m0h + r) * N_F + kb * 32 + k];
                    }
#pragma unroll
                    for (int it = 0; it < 8; it++) {
                        int idx = tid + it * 256;
                        int r = idx >> 5, k = idx & 31;
                        Hs[r * 33 + k] = g_H[(size_t)(col0 + r) * N_F + kb * 32 + k];
                    }
                    __syncthreads();
#pragma unroll
                    for (int k = 0; k < 32; k++) {
                        float a8[8], b4[4];
#pragma unroll
                        for (int i = 0; i < 8; i++) a8[i] = Xs[(ty * 8 + i) * 33 + k];
#pragma unroll
                        for (int j = 0; j < 4; j++) b4[j] = Hs[(tx * 4 + j) * 33 + k];
#pragma unroll
                        for (int i = 0; i < 8; i++)
#pragma unroll
                            for (int j = 0; j < 4; j++)
                                acc[i][j] = fmaf(a8[i], b4[j], acc[i][j]);
                    }
                    __syncthreads();
                }
#pragma unroll
                for (int i = 0; i < 8; i++)
#pragma unroll
                    for (int j = 0; j < 4; j++) {
                        int col = col0 + tx * 4 + j;
                        out[(size_t)(m0h + ty * 8 + i) * N_F + col] = acc[i][j] + bias[col];
                    }
            }
        }
    }
#endif
}

// ---------------------------------------------------------------------------
// Host launcher
// ---------------------------------------------------------------------------
typedef CUresult (*PFN_encodeTiled)(
    CUtensorMap*, CUtensorMapDataType, cuuint32_t, void*,
    const cuuint64_t*, const cuuint64_t*, const cuuint32_t*, const cuuint32_t*,
    CUtensorMapInterleave, CUtensorMapSwizzle, CUtensorMapL2promotion,
    CUtensorMapFloatOOBfill);

extern "C" void kernel_launch(void* const* d_in, const int* in_sizes, int n_in,
                              void* d_out, int out_size) {
    const float* x    = (const float*)d_in[0];
    const float* A    = (const float*)d_in[1];
    const float* S    = (const float*)d_in[2];
    const float* bias = (const float*)d_in[3];
    float* out = (float*)d_out;

    long Mrows = (long)in_sizes[0] / N_F;   // 131072
    int ntiles = (int)(Mrows / 256) * 2;    // fallback path only

    build_H<<<N_F, N_F>>>(A, S);

    void* hptr = nullptr;
    cudaGetSymbolAddress(&hptr, g_H);

    // Resolve cuTensorMapEncodeTiled via the runtime (no -lcuda needed).
    PFN_encodeTiled enc = nullptr;
    {
        cudaDriverEntryPointQueryResult st;
        cudaGetDriverEntryPointByVersion("cuTensorMapEncodeTiled", (void**)&enc,
                                         12050, cudaEnableDefault, &st);
    }

    CUtensorMap mx{}, mh{};
    if (enc) {
        {
            cuuint64_t dims[2]    = {(cuuint64_t)N_F, (cuuint64_t)Mrows};
            cuuint64_t strides[1] = {(cuuint64_t)N_F * 4};
            cuuint32_t box[2]     = {KC, 128};       // 64B x 128 rows (X sub-tile)
            cuuint32_t es[2]      = {1, 1};
            enc(&mx, CU_TENSOR_MAP_DATA_TYPE_FLOAT32, 2, (void*)x,
                dims, strides, box, es,
                CU_TENSOR_MAP_INTERLEAVE_NONE, CU_TENSOR_MAP_SWIZZLE_64B,
                CU_TENSOR_MAP_L2_PROMOTION_L2_128B, CU_TENSOR_MAP_FLOAT_OOB_FILL_NONE);
        }
        {
            cuuint64_t dims[2]    = {(cuuint64_t)N_F, (cuuint64_t)N_F};
            cuuint64_t strides[1] = {(cuuint64_t)N_F * 4};
            cuuint32_t box[2]     = {KC, 256};       // 64B x 256 rows (H half)
            cuuint32_t es[2]      = {1, 1};
            enc(&mh, CU_TENSOR_MAP_DATA_TYPE_FLOAT32, 2, hptr,
                dims, strides, box, es,
                CU_TENSOR_MAP_INTERLEAVE_NONE, CU_TENSOR_MAP_SWIZZLE_64B,
                CU_TENSOR_MAP_L2_PROMOTION_L2_128B, CU_TENSOR_MAP_FLOAT_OOB_FILL_NONE);
        }
    }

    cudaFuncSetAttribute(phm_gemm, cudaFuncAttributeMaxDynamicSharedMemorySize, SMEM_BYTES);
    phm_gemm<<<GRID, 256, SMEM_BYTES>>>(x, bias, out, ntiles, mx, mh);
}

// round 10
// speedup vs baseline: 1.9309x; 1.9309x over previous
#include <cuda_runtime.h>
#include <cuda.h>
#include <cstdint>

// ============================================================================
// PHM8Linear: out[131072,512] = X[131072,512] @ H[512,512]^T + bias
// H[a*64+b][c*64+d] = sum_i A[i,a,c] * S[i,b,d]
// tcgen05 TF32 cta_group::2 SS GEMM, persistent grid=148, cluster (2,1,1).
// Pair {2c,2c+1} jointly computes M=256 x N=512 tiles: rank r holds X rows
// [m0+r*128) (A half) and H rows r*128 of each 256-row column block (B half).
// Per chunk per SM: 48KB (byte-optimal). D0 = tmem cols 0-255 (out 0-255),
// D1 = cols 256-511. 4-stage x 48KB ring. rank0 warp0 = MMA dispatcher,
// rank1 warp0 = full-forwarder, warp1 = TMA producer (both), warps 2-7 =
// epilogue (both). X raw fp32 (HW tf32 truncate); H pre-rounded RN.
// ============================================================================

#define N_F    512
#define KC     32          // K elems per chunk = 128 bytes = SW128 row
#define NSTAGE 4
#define GRID   148
#define NPAIR  74
#define M_TILES 512        // 131072/256

__device__ float g_H[N_F * N_F];   // precomputed H (tf32-rounded fp32 bits)

#if defined(__CUDA_ARCH__) && (defined(__CUDA_ARCH_FEAT_SM103_ALL) || \
    defined(__CUDA_ARCH_FEAT_SM100_ALL) || defined(__CUDA_ARCH_FEAT_SM101_ALL))
#define HAS_TCGEN05 1
#else
#define HAS_TCGEN05 0
#endif

// ---------------- smem layout (dynamic), tcgen05 path ----------------
// Stage (48KB): X 16KB @+0 | H0 16KB @+16384 | H1 16KB @+32768
#define OFF_TPTR    0
#define OFF_FULL(s) (8 + 8 * (s))
#define OFF_DONE(s) (48 + 8 * (s))
#define OFF_EPI     96
#define OFF_DFREE   104
#define OFF_STG(s)  (1024 + (s) * 49152)
#define SMEM_BYTES  (1024 + NSTAGE * 49152)
#define STAGE_BYTES 49152u

// idesc: kind::tf32, D=F32(1<<4), A=TF32(2<<7), B=TF32(2<<10), N=256, M=256
#define IDESC_TF32_CG2 ((1u << 4) | (2u << 7) | (2u << 10) | ((256u / 8u) << 17) | ((256u / 16u) << 24))

// K-major SW128 smem descriptor base: layout=SW128(2), version=1, SBO=64, LBO=1
static __device__ __host__ constexpr uint64_t DESC_BASE_SW128 =
    (uint64_t(2) << 61) | (uint64_t(1) << 46) | (uint64_t(64) << 32) | (uint64_t(1) << 16);

__device__ __forceinline__ uint32_t s2u(const void* p) {
    uint32_t a;
    asm("{ .reg .u64 t; cvta.to.shared.u64 t, %1; cvt.u32.u64 %0, t; }" : "=r"(a) : "l"(p));
    return a;
}

#define MBAR_INIT(addr, cnt) \
    asm volatile("mbarrier.init.shared.b64 [%0], %1;" :: "r"(addr), "r"(cnt) : "memory")

#define MBAR_ARRIVE(addr) \
    asm volatile("mbarrier.arrive.shared.b64 _, [%0];" :: "r"(addr) : "memory")

// Arrive on the same-offset mbarrier in cluster CTA `rank` (here rank 0).
#define MBAR_ARRIVE_CLUSTER0(addr)                                             \
    asm volatile("{\n\t.reg .b32 ra;\n\t"                                      \
        "mapa.shared::cluster.u32 ra, %0, %1;\n\t"                             \
        "mbarrier.arrive.shared::cluster.b64 _, [ra];\n\t}"                    \
        :: "r"(addr), "r"(0) : "memory")

#define MBAR_EXPECT_TX(addr, bytes) \
    asm volatile("mbarrier.arrive.expect_tx.shared.b64 _, [%0], %1;" :: "r"(addr), "r"(bytes) : "memory")

#define MBAR_WAIT_SCOPE(addr, parity, SCOPE) do {                              \
    uint32_t _mb = (addr); uint32_t _ph = (parity); uint32_t _dn;              \
    asm volatile("{\n\t.reg .pred p;\n\t"                                      \
        "mbarrier.try_wait.parity.acquire." SCOPE ".shared::cta.b64 p, [%1], %2;\n\t" \
        "selp.b32 %0, 1, 0, p;\n\t}" : "=r"(_dn) : "r"(_mb), "r"(_ph) : "memory"); \
    while (!_dn) {                                                             \
        asm volatile("{\n\t.reg .pred p;\n\t"                                  \
            "mbarrier.try_wait.parity.acquire." SCOPE ".shared::cta.b64 p, [%1], %2, 0x989680;\n\t" \
            "selp.b32 %0, 1, 0, p;\n\t}" : "=r"(_dn) : "r"(_mb), "r"(_ph) : "memory"); \
    }                                                                          \
} while (0)

#define MBAR_WAIT(addr, parity)     MBAR_WAIT_SCOPE(addr, parity, "cta")
#define MBAR_WAIT_CLU(addr, parity) MBAR_WAIT_SCOPE(addr, parity, "cluster")

#define TMA2D(smem, map, cx, cy, mbar)                                         \
    asm volatile("cp.async.bulk.tensor.2d.shared::cta.global.tile.mbarrier::complete_tx::bytes " \
        "[%0], [%1, {%2, %3}], [%4];"                                          \
        :: "r"(smem), "l"(map), "r"(cx), "r"(cy), "r"(mbar) : "memory")

// cta_group::2 tf32 MMA (leader issues; A/B split across the CTA pair)
#define MMA_TF32_CG2(dst, adsc, bdsc, en)                                      \
    asm volatile("{\n\t.reg .pred p;\n\tsetp.ne.u32 p, %5, 0;\n\t"             \
        "tcgen05.mma.cta_group::2.kind::tf32 [%0], %1, %2, %3, "               \
        "{%4,%4,%4,%4,%4,%4,%4,%4}, p;\n\t}"                                   \
        :: "r"(dst), "l"(adsc), "l"(bdsc), "r"(IDESC_TF32_CG2), "r"(0u), "r"(en) : "memory")

#define TC_COMMIT_MC_CG2(mbar, mask)                                           \
    asm volatile("tcgen05.commit.cta_group::2.mbarrier::arrive::one.shared::cluster.multicast::cluster.b64 [%0], %1;" \
        :: "r"(mbar), "h"((uint16_t)(mask)) : "memory")

#define CLUSTER_SYNC() do {                                                    \
    asm volatile("barrier.cluster.arrive.aligned;" ::: "memory");              \
    asm volatile("barrier.cluster.wait.aligned;" ::: "memory");                \
} while (0)

// ---------------------------------------------------------------------------
// H precompute: H[r=a*64+b][k=c*64+d] = sum_i A[i,a,c]*S[i,b,d], RN->tf32
// ---------------------------------------------------------------------------
__global__ void build_H(const float* __restrict__ A, const float* __restrict__ S) {
    int r = blockIdx.x;     // 0..511
    int k = threadIdx.x;    // 0..511
    int a = r >> 6, bb = r & 63, c = k >> 6, d = k & 63;
    float acc = 0.f;
#pragma unroll
    for (int i = 0; i < 8; i++)
        acc = fmaf(A[i * 64 + a * 8 + c], S[i * 4096 + bb * 64 + d], acc);
    uint32_t t;
    asm("cvt.rna.tf32.f32 %0, %1;" : "=r"(t) : "f"(acc));
    g_H[r * N_F + k] = __uint_as_float(t);
}

// ---------------------------------------------------------------------------
// Main GEMM kernel
// ---------------------------------------------------------------------------
__global__ void __launch_bounds__(256, 1) __cluster_dims__(2, 1, 1) phm_gemm(
    const float* __restrict__ x,
    const float* __restrict__ bias, float* __restrict__ out,
    int ntiles,
    const __grid_constant__ CUtensorMap mx,
    const __grid_constant__ CUtensorMap mh)
{
    int bid = blockIdx.x;

#if HAS_TCGEN05
    // =================== tcgen05 TF32 cg2 path (sm_103a) ==================
    (void)x; (void)ntiles;
    extern __shared__ char smem_raw[];
    uint32_t sb = s2u(smem_raw);
    int tid = threadIdx.x, wid = tid >> 5, lid = tid & 31;

    int c    = bid >> 1;        // pair id (0..73)
    int rank = bid & 1;         // cluster rank
    int cnt  = 1 + (M_TILES - 1 - c) / NPAIR;   // tiles for this pair

    if (wid == 0) {
        asm volatile("tcgen05.alloc.cta_group::2.sync.aligned.shared::cta.b32 [%0], %1;"
                     :: "r"(sb + OFF_TPTR), "r"(512) : "memory");
        asm volatile("tcgen05.relinquish_alloc_permit.cta_group::2.sync.aligned;");
    }
    if (tid == 0) {
#pragma unroll
        for (int s = 0; s < NSTAGE; s++) {
            // leader full: own expect arrive + rank1's forwarded arrive
            MBAR_INIT(sb + OFF_FULL(s), rank == 0 ? 2 : 1);
            MBAR_INIT(sb + OFF_DONE(s), 1);
        }
        MBAR_INIT(sb + OFF_EPI, 1);
        MBAR_INIT(sb + OFF_DFREE, 12);   // 6 warps x 2 CTAs
    }
    __syncthreads();
    uint32_t tmem;
    asm volatile("ld.shared.b32 %0, [%1];" : "=r"(tmem) : "r"(sb + OFF_TPTR));

    // All mbarriers live in both CTAs before any cross-CTA traffic.
    CLUSTER_SYNC();

    if (wid == 0 && lid == 0) {
        if (rank == 0) {
            // ---------------- MMA dispatcher (leader only) ----------------
            uint64_t dX[NSTAGE], dH0[NSTAGE], dH1[NSTAGE];
#pragma unroll
            for (int s = 0; s < NSTAGE; s++) {
                dX[s]  = DESC_BASE_SW128 | (((sb + OFF_STG(s))         >> 4) & 0x3FFF);
                dH0[s] = DESC_BASE_SW128 | (((sb + OFF_STG(s) + 16384) >> 4) & 0x3FFF);
                dH1[s] = DESC_BASE_SW128 | (((sb + OFF_STG(s) + 32768) >> 4) & 0x3FFF);
            }
            int cs = 0, ph = 0;
            for (int j = 0; j < cnt; j++) {
                for (int k = 0; k < 16; k++) {
                    if (k == 0 && j > 0) {
                        // D reused: both CTAs' epilogues must have read tile j-1
                        MBAR_WAIT(sb + OFF_DFREE, (j - 1) & 1);
                        asm volatile("tcgen05.fence::after_thread_sync;" ::: "memory");
                    }
                    MBAR_WAIT_CLU(sb + OFF_FULL(cs), ph);
#pragma unroll
                    for (int ks = 0; ks < 4; ks++) {
                        uint32_t en = (k | ks) ? 1u : 0u;
                        MMA_TF32_CG2(tmem,       dX[cs] + 2 * ks, dH0[cs] + 2 * ks, en);
                        MMA_TF32_CG2(tmem + 256, dX[cs] + 2 * ks, dH1[cs] + 2 * ks, en);
                    }
                    TC_COMMIT_MC_CG2(sb + OFF_DONE(cs), 3);
                    if (k == 15) TC_COMMIT_MC_CG2(sb + OFF_EPI, 3);
                    if (++cs == NSTAGE) { cs = 0; ph ^= 1; }
                }
            }
        } else {
            // ------------- full-forwarder (rank 1) -------------
            // Forward each local stage-full completion to the leader's barrier.
            int cs = 0, ph = 0;
            int P = 16 * cnt;
            for (int p = 0; p < P; p++) {
                MBAR_WAIT(sb + OFF_FULL(cs), ph);
                MBAR_ARRIVE_CLUSTER0(sb + OFF_FULL(cs));
                if (++cs == NSTAGE) { cs = 0; ph ^= 1; }
            }
        }
    } else if (wid == 1 && lid == 0) {
        // ---------------- TMA producer (both ranks) ----------------
        int cs = 0, ph = 0, filled = 0;
        for (int j = 0; j < cnt; j++) {
            int m0 = (c + NPAIR * j) * 256;
            for (int k = 0; k < 16; k++) {
                if (filled >= NSTAGE)
                    MBAR_WAIT(sb + OFF_DONE(cs), ph ^ 1);   // stage drained (mc commit)
                MBAR_EXPECT_TX(sb + OFF_FULL(cs), STAGE_BYTES);
                TMA2D(sb + OFF_STG(cs),         &mx, k * KC, m0 + rank * 128,  sb + OFF_FULL(cs));
                TMA2D(sb + OFF_STG(cs) + 16384, &mh, k * KC, rank * 128,       sb + OFF_FULL(cs));
                TMA2D(sb + OFF_STG(cs) + 32768, &mh, k * KC, 256 + rank * 128, sb + OFF_FULL(cs));
                filled++;
                if (++cs == NSTAGE) { cs = 0; ph ^= 1; }
            }
        }
    } else if (wid >= 2) {
        // ---------------- epilogue warps (2..7, both ranks) ----------------
        // subpartition sp covered by: sp0=warp4 (16 chunks), sp1=warp5 (16),
        // sp2=warps2/6 (8+8), sp3=warps3/7 (8+8). 512 cols per CTA tile.
        int sp = wid & 3;
        int nch = (sp < 2) ? 16 : 8;
        int ch0 = (sp < 2) ? 0 : ((wid >= 6) ? 8 : 0);
        for (int j = 0; j < cnt; j++) {
            MBAR_WAIT(sb + OFF_EPI, j & 1);
            asm volatile("tcgen05.fence::after_thread_sync;" ::: "memory");

            size_t row = (size_t)((c + NPAIR * j) * 256 + rank * 128 + sp * 32 + lid);
            float* orow = out + row * N_F;
            for (int cc = 0; cc < nch; cc++) {
                int c0 = (ch0 + cc) * 32;
                uint32_t r[32];
                asm volatile(
                    "tcgen05.ld.sync.aligned.32x32b.x32.b32 "
                    "{%0, %1, %2, %3, %4, %5, %6, %7, "
                    " %8, %9, %10, %11, %12, %13, %14, %15, "
                    " %16, %17, %18, %19, %20, %21, %22, %23, "
                    " %24, %25, %26, %27, %28, %29, %30, %31}, [%32];"
                    : "=r"(r[0]),  "=r"(r[1]),  "=r"(r[2]),  "=r"(r[3]),
                      "=r"(r[4]),  "=r"(r[5]),  "=r"(r[6]),  "=r"(r[7]),
                      "=r"(r[8]),  "=r"(r[9]),  "=r"(r[10]), "=r"(r[11]),
                      "=r"(r[12]), "=r"(r[13]), "=r"(r[14]), "=r"(r[15]),
                      "=r"(r[16]), "=r"(r[17]), "=r"(r[18]), "=r"(r[19]),
                      "=r"(r[20]), "=r"(r[21]), "=r"(r[22]), "=r"(r[23]),
                      "=r"(r[24]), "=r"(r[25]), "=r"(r[26]), "=r"(r[27]),
                      "=r"(r[28]), "=r"(r[29]), "=r"(r[30]), "=r"(r[31])
                    : "r"(tmem + c0));
                asm volatile("tcgen05.wait::ld.sync.aligned;" ::: "memory");
                if (cc == nch - 1) {
                    // D cols read into regs -> release dispatcher (leader DFREE)
                    asm volatile("tcgen05.fence::before_thread_sync;" ::: "memory");
                    if (lid == 0) {
                        if (rank == 0) { MBAR_ARRIVE(sb + OFF_DFREE); }
                        else           { MBAR_ARRIVE_CLUSTER0(sb + OFF_DFREE); }
                    }
                }
#pragma unroll
                for (int q = 0; q < 8; q++) {
                    float4 bv = *reinterpret_cast<const float4*>(bias + c0 + q * 4);
                    float4 v;
                    v.x = __uint_as_float(r[q * 4 + 0]) + bv.x;
                    v.y = __uint_as_float(r[q * 4 + 1]) + bv.y;
                    v.z = __uint_as_float(r[q * 4 + 2]) + bv.z;
                    v.w = __uint_as_float(r[q * 4 + 3]) + bv.w;
                    *reinterpret_cast<float4*>(orow + c0 + q * 4) = v;
                }
            }
        }
    }

    __syncthreads();
    // Peer may still be MMA-reading our SMEM / arriving on our barriers.
    CLUSTER_SYNC();
    if (wid == 0) {
        asm volatile("tcgen05.dealloc.cta_group::2.sync.aligned.b32 %0, %1;"
                     :: "r"(tmem), "r"(512));
    }

#else
    // =================== SIMT fp32 fallback (non-'a' pass) ================
    (void)mx; (void)mh;
    extern __shared__ char smem_raw[];
    float* Xs = reinterpret_cast<float*>(smem_raw);          // [128][33]
    float* Hs = Xs + 128 * 33;                               // [64][33]

    int tid = threadIdx.x;
    int ty = tid >> 4, tx = tid & 15;

    for (int g = bid; g < ntiles; g += GRID) {
        int m0 = (g >> 1) * 256;
        int nb = g & 1;
        for (int half = 0; half < 2; half++) {
            int m0h = m0 + half * 128;
            for (int nc = 0; nc < 4; nc++) {
                int col0 = nb * 256 + nc * 64;
                float acc[8][4];
#pragma unroll
                for (int i = 0; i < 8; i++)
#pragma unroll
                    for (int j = 0; j < 4; j++) acc[i][j] = 0.f;

                for (int kb = 0; kb < 16; kb++) {
#pragma unroll
                    for (int it = 0; it < 16; it++) {
                        int idx = tid + it * 256;
                        int r = idx >> 5, k = idx & 31;
                        Xs[r * 33 + k] = x[(size_t)(m0h + r) * N_F + kb * 32 + k];
                    }
#pragma unroll
                    for (int it = 0; it < 8; it++) {
                        int idx = tid + it * 256;
                        int r = idx >> 5, k = idx & 31;
                        Hs[r * 33 + k] = g_H[(size_t)(col0 + r) * N_F + kb * 32 + k];
                    }
                    __syncthreads();
#pragma unroll
                    for (int k = 0; k < 32; k++) {
                        float a8[8], b4[4];
#pragma unroll
                        for (int i = 0; i < 8; i++) a8[i] = Xs[(ty * 8 + i) * 33 + k];
#pragma unroll
                        for (int j = 0; j < 4; j++) b4[j] = Hs[(tx * 4 + j) * 33 + k];
#pragma unroll
                        for (int i = 0; i < 8; i++)
#pragma unroll
                            for (int j = 0; j < 4; j++)
                                acc[i][j] = fmaf(a8[i], b4[j], acc[i][j]);
                    }
                    __syncthreads();
                }
#pragma unroll
                for (int i = 0; i < 8; i++)
#pragma unroll
                    for (int j = 0; j < 4; j++) {
                        int col = col0 + tx * 4 + j;
                        out[(size_t)(m0h + ty * 8 + i) * N_F + col] = acc[i][j] + bias[col];
                    }
            }
        }
    }
#endif
}

// ---------------------------------------------------------------------------
// Host launcher
// ---------------------------------------------------------------------------
typedef CUresult (*PFN_encodeTiled)(
    CUtensorMap*, CUtensorMapDataType, cuuint32_t, void*,
    const cuuint64_t*, const cuuint64_t*, const cuuint32_t*, const cuuint32_t*,
    CUtensorMapInterleave, CUtensorMapSwizzle, CUtensorMapL2promotion,
    CUtensorMapFloatOOBfill);

extern "C" void kernel_launch(void* const* d_in, const int* in_sizes, int n_in,
                              void* d_out, int out_size) {
    const float* x    = (const float*)d_in[0];
    const float* A    = (const float*)d_in[1];
    const float* S    = (const float*)d_in[2];
    const float* bias = (const float*)d_in[3];
    float* out = (float*)d_out;

    long Mrows = (long)in_sizes[0] / N_F;   // 131072
    int ntiles = (int)(Mrows / 256) * 2;    // fallback path only

    build_H<<<N_F, N_F>>>(A, S);

    void* hptr = nullptr;
    cudaGetSymbolAddress(&hptr, g_H);

    // Resolve cuTensorMapEncodeTiled via the runtime (no -lcuda needed).
    PFN_encodeTiled enc = nullptr;
    {
        cudaDriverEntryPointQueryResult st;
        cudaGetDriverEntryPointByVersion("cuTensorMapEncodeTiled", (void**)&enc,
                                         12050, cudaEnableDefault, &st);
    }

    CUtensorMap mx{}, mh{};
    if (enc) {
        {
            cuuint64_t dims[2]    = {(cuuint64_t)N_F, (cuuint64_t)Mrows};
            cuuint64_t strides[1] = {(cuuint64_t)N_F * 4};
            cuuint32_t box[2]     = {KC, 128};       // 128B x 128 rows (X half)
            cuuint32_t es[2]      = {1, 1};
            enc(&mx, CU_TENSOR_MAP_DATA_TYPE_FLOAT32, 2, (void*)x,
                dims, strides, box, es,
                CU_TENSOR_MAP_INTERLEAVE_NONE, CU_TENSOR_MAP_SWIZZLE_128B,
                CU_TENSOR_MAP_L2_PROMOTION_L2_128B, CU_TENSOR_MAP_FLOAT_OOB_FILL_NONE);
        }
        {
            cuuint64_t dims[2]    = {(cuuint64_t)N_F, (cuuint64_t)N_F};
            cuuint64_t strides[1] = {(cuuint64_t)N_F * 4};
            cuuint32_t box[2]     = {KC, 128};       // 128B x 128 rows (H quarter)
            cuuint32_t es[2]      = {1, 1};
            enc(&mh, CU_TENSOR_MAP_DATA_TYPE_FLOAT32, 2, hptr,
                dims, strides, box, es,
                CU_TENSOR_MAP_INTERLEAVE_NONE, CU_TENSOR_MAP_SWIZZLE_128B,
                CU_TENSOR_MAP_L2_PROMOTION_L2_128B, CU_TENSOR_MAP_FLOAT_OOB_FILL_NONE);
        }
    }

    cudaFuncSetAttribute(phm_gemm, cudaFuncAttributeMaxDynamicSharedMemorySize, SMEM_BYTES);
    phm_gemm<<<GRID, 256, SMEM_BYTES>>>(x, bias, out, ntiles, mx, mh);
}

// round 11
// speedup vs baseline: 1.9744x; 1.0226x over previous
#include <cuda_runtime.h>
#include <cuda.h>
#include <cstdint>

// ============================================================================
// PHM8Linear: out[131072,512] = X[131072,512] @ H[512,512]^T + bias
// H[a*64+b][c*64+d] = sum_i A[i,a,c] * S[i,b,d]
// tcgen05 TF32 cta_group::2 SS GEMM, persistent grid=148, cluster (2,1,1).
// Pair {2c,2c+1} jointly computes M=256 x N=512 tiles; 48KB/SM/chunk (optimal).
// R11: cg2 TMA lands on leader's barrier (no forwarder); epilogue split per
// N-half (EPI0/EPI1, DFREE0/DFREE1) with lookahead-4 D0 burst at tile
// boundaries so the epilogue overlaps next-tile MMAs. H as one 3D TMA box.
// X raw fp32 (HW tf32 truncate); H pre-rounded RN in build_H.
// ============================================================================

#define N_F    512
#define KC     32          // K elems per chunk = 128 bytes = SW128 row
#define NSTAGE 4
#define GRID   148
#define NPAIR  74
#define M_TILES 512        // 131072/256

__device__ float g_H[N_F * N_F];   // precomputed H (tf32-rounded fp32 bits)

#if defined(__CUDA_ARCH__) && (defined(__CUDA_ARCH_FEAT_SM103_ALL) || \
    defined(__CUDA_ARCH_FEAT_SM100_ALL) || defined(__CUDA_ARCH_FEAT_SM101_ALL))
#define HAS_TCGEN05 1
#else
#define HAS_TCGEN05 0
#endif

// ---------------- smem layout (dynamic), tcgen05 path ----------------
// Stage (48KB): X 16KB @+0 | H0 16KB @+16384 | H1 16KB @+32768
#define OFF_TPTR    0
#define OFF_FULL(s) (8 + 8 * (s))
#define OFF_DONE(s) (48 + 8 * (s))
#define OFF_EPI0    96
#define OFF_EPI1    104
#define OFF_DFREE0  112
#define OFF_DFREE1  120
#define OFF_STG(s)  (1024 + (s) * 49152)
#define SMEM_BYTES  (1024 + NSTAGE * 49152)
#define EXPECT_PAIR 98304u    // 48KB x 2 CTAs onto leader's barrier

// idesc: kind::tf32, D=F32(1<<4), A=TF32(2<<7), B=TF32(2<<10), N=256, M=256
#define IDESC_TF32_CG2 ((1u << 4) | (2u << 7) | (2u << 10) | ((256u / 8u) << 17) | ((256u / 16u) << 24))

// K-major SW128 smem descriptor base: layout=SW128(2), version=1, SBO=64, LBO=1
static __device__ __host__ constexpr uint64_t DESC_BASE_SW128 =
    (uint64_t(2) << 61) | (uint64_t(1) << 46) | (uint64_t(64) << 32) | (uint64_t(1) << 16);

__device__ __forceinline__ uint32_t s2u(const void* p) {
    uint32_t a;
    asm("{ .reg .u64 t; cvta.to.shared.u64 t, %1; cvt.u32.u64 %0, t; }" : "=r"(a) : "l"(p));
    return a;
}

#define MBAR_INIT(addr, cnt) \
    asm volatile("mbarrier.init.shared.b64 [%0], %1;" :: "r"(addr), "r"(cnt) : "memory")

#define MBAR_ARRIVE(addr) \
    asm volatile("mbarrier.arrive.shared.b64 _, [%0];" :: "r"(addr) : "memory")

// Arrive on the same-offset mbarrier in cluster CTA rank 0.
#define MBAR_ARRIVE_CLUSTER0(addr)                                             \
    asm volatile("{\n\t.reg .b32 ra;\n\t"                                      \
        "mapa.shared::cluster.u32 ra, %0, %1;\n\t"                             \
        "mbarrier.arrive.shared::cluster.b64 _, [ra];\n\t}"                    \
        :: "r"(addr), "r"(0) : "memory")

#define MBAR_EXPECT_TX(addr, bytes) \
    asm volatile("mbarrier.arrive.expect_tx.shared.b64 _, [%0], %1;" :: "r"(addr), "r"(bytes) : "memory")

#define MBAR_WAIT_SCOPE(addr, parity, SCOPE) do {                              \
    uint32_t _mb = (addr); uint32_t _ph = (parity); uint32_t _dn;              \
    asm volatile("{\n\t.reg .pred p;\n\t"                                      \
        "mbarrier.try_wait.parity.acquire." SCOPE ".shared::cta.b64 p, [%1], %2;\n\t" \
        "selp.b32 %0, 1, 0, p;\n\t}" : "=r"(_dn) : "r"(_mb), "r"(_ph) : "memory"); \
    while (!_dn) {                                                             \
        asm volatile("{\n\t.reg .pred p;\n\t"                                  \
            "mbarrier.try_wait.parity.acquire." SCOPE ".shared::cta.b64 p, [%1], %2, 0x989680;\n\t" \
            "selp.b32 %0, 1, 0, p;\n\t}" : "=r"(_dn) : "r"(_mb), "r"(_ph) : "memory"); \
    }                                                                          \
} while (0)

#define MBAR_WAIT(addr, parity)     MBAR_WAIT_SCOPE(addr, parity, "cta")
#define MBAR_WAIT_CLU(addr, parity) MBAR_WAIT_SCOPE(addr, parity, "cluster")

// cta_group::2 TMA: both CTAs execute; complete_tx targets leader's barrier
// (bit 24 cleared). Data lands in the ISSUING CTA's smem.
#define TMA3D_CG2(smem, map, cx, cy, cz, mbar)                                 \
    asm volatile("{\n\t.reg .b32 lb;\n\t"                                      \
        "and.b32 lb, %5, 0xFEFFFFFF;\n\t"                                      \
        "cp.async.bulk.tensor.3d.cta_group::2.shared::cluster.global"          \
        ".tile.mbarrier::complete_tx::bytes [%0], [%1, {%2, %3, %4}], [lb];\n\t}" \
        :: "r"(smem), "l"(map), "r"(cx), "r"(cy), "r"(cz), "r"(mbar) : "memory")

// cta_group::2 tf32 MMA (leader issues; A/B split across the CTA pair)
#define MMA_TF32_CG2(dst, adsc, bdsc, en)                                      \
    asm volatile("{\n\t.reg .pred p;\n\tsetp.ne.u32 p, %5, 0;\n\t"             \
        "tcgen05.mma.cta_group::2.kind::tf32 [%0], %1, %2, %3, "               \
        "{%4,%4,%4,%4,%4,%4,%4,%4}, p;\n\t}"                                   \
        :: "r"(dst), "l"(adsc), "l"(bdsc), "r"(IDESC_TF32_CG2), "r"(0u), "r"(en) : "memory")

#define TC_COMMIT_MC_CG2(mbar)                                                 \
    asm volatile("tcgen05.commit.cta_group::2.mbarrier::arrive::one.shared::cluster.multicast::cluster.b64 [%0], %1;" \
        :: "r"(mbar), "h"((uint16_t)3) : "memory")

#define CLUSTER_SYNC() do {                                                    \
    asm volatile("barrier.cluster.arrive.aligned;" ::: "memory");              \
    asm volatile("barrier.cluster.wait.aligned;" ::: "memory");                \
} while (0)

// ---------------------------------------------------------------------------
// H precompute: H[r=a*64+b][k=c*64+d] = sum_i A[i,a,c]*S[i,b,d], RN->tf32
// ---------------------------------------------------------------------------
__global__ void build_H(const float* __restrict__ A, const float* __restrict__ S) {
    int r = blockIdx.x;     // 0..511
    int k = threadIdx.x;    // 0..511
    int a = r >> 6, bb = r & 63, c = k >> 6, d = k & 63;
    float acc = 0.f;
#pragma unroll
    for (int i = 0; i < 8; i++)
        acc = fmaf(A[i * 64 + a * 8 + c], S[i * 4096 + bb * 64 + d], acc);
    uint32_t t;
    asm("cvt.rna.tf32.f32 %0, %1;" : "=r"(t) : "f"(acc));
    g_H[r * N_F + k] = __uint_as_float(t);
}

// ---------------------------------------------------------------------------
// Main GEMM kernel
// ---------------------------------------------------------------------------
__global__ void __launch_bounds__(256, 1) __cluster_dims__(2, 1, 1) phm_gemm(
    const float* __restrict__ x,
    const float* __restrict__ bias, float* __restrict__ out,
    int ntiles,
    const __grid_constant__ CUtensorMap mx,
    const __grid_constant__ CUtensorMap mh)
{
    int bid = blockIdx.x;

#if HAS_TCGEN05
    // =================== tcgen05 TF32 cg2 path (sm_103a) ==================
    (void)x; (void)ntiles;
    extern __shared__ char smem_raw[];
    uint32_t sb = s2u(smem_raw);
    int tid = threadIdx.x, wid = tid >> 5, lid = tid & 31;

    int c    = bid >> 1;        // pair id (0..73)
    int rank = bid & 1;         // cluster rank
    int cnt  = 1 + (M_TILES - 1 - c) / NPAIR;   // tiles for this pair

    if (wid == 0) {
        asm volatile("tcgen05.alloc.cta_group::2.sync.aligned.shared::cta.b32 [%0], %1;"
                     :: "r"(sb + OFF_TPTR), "r"(512) : "memory");
        asm volatile("tcgen05.relinquish_alloc_permit.cta_group::2.sync.aligned;");
    }
    if (tid == 0) {
#pragma unroll
        for (int s = 0; s < NSTAGE; s++) {
            MBAR_INIT(sb + OFF_FULL(s), 1);   // leader: 1 expect arrive, 96KB tx
            MBAR_INIT(sb + OFF_DONE(s), 1);
        }
        MBAR_INIT(sb + OFF_EPI0, 1);
        MBAR_INIT(sb + OFF_EPI1, 1);
        MBAR_INIT(sb + OFF_DFREE0, 12);      // 6 epilogue warps x 2 CTAs
        MBAR_INIT(sb + OFF_DFREE1, 12);
    }
    __syncthreads();
    uint32_t tmem;
    asm volatile("ld.shared.b32 %0, [%1];" : "=r"(tmem) : "r"(sb + OFF_TPTR));

    // All mbarriers live in both CTAs before any cross-CTA TMA/commit.
    CLUSTER_SYNC();

    if (wid == 0 && lid == 0 && rank == 0) {
        // ---------------- MMA dispatcher (leader only) ----------------
        uint64_t dX[NSTAGE], dH0[NSTAGE], dH1[NSTAGE];
#pragma unroll
        for (int s = 0; s < NSTAGE; s++) {
            dX[s]  = DESC_BASE_SW128 | (((sb + OFF_STG(s))         >> 4) & 0x3FFF);
            dH0[s] = DESC_BASE_SW128 | (((sb + OFF_STG(s) + 16384) >> 4) & 0x3FFF);
            dH1[s] = DESC_BASE_SW128 | (((sb + OFF_STG(s) + 32768) >> 4) & 0x3FFF);
        }
        int ph = 0;   // full-parity of current wrap (tile-aligned: 16 pos = 4 wraps)
        for (int j = 0; j < cnt; j++) {
            // ---- positions 0..3: D0 burst (overlaps epilogue's D1 read) ----
            if (j > 0) {
                MBAR_WAIT(sb + OFF_DFREE0, (j - 1) & 1);
                asm volatile("tcgen05.fence::after_thread_sync;" ::: "memory");
            }
#pragma unroll
            for (int q = 0; q < 4; q++) {
                MBAR_WAIT_CLU(sb + OFF_FULL(q), ph);
#pragma unroll
                for (int ks = 0; ks < 4; ks++)
                    MMA_TF32_CG2(tmem, dX[q] + 2 * ks, dH0[q] + 2 * ks, (q | ks) ? 1u : 0u);
            }
            if (j > 0) {
                MBAR_WAIT(sb + OFF_DFREE1, (j - 1) & 1);
                asm volatile("tcgen05.fence::after_thread_sync;" ::: "memory");
            }
#pragma unroll
            for (int q = 0; q < 4; q++) {
#pragma unroll
                for (int ks = 0; ks < 4; ks++)
                    MMA_TF32_CG2(tmem + 256, dX[q] + 2 * ks, dH1[q] + 2 * ks, (q | ks) ? 1u : 0u);
                TC_COMMIT_MC_CG2(sb + OFF_DONE(q));
            }
            ph ^= 1;
            // ---- positions 4..15: steady ----
            for (int p = 4; p < 16; p++) {
                int s = p & 3;
                MBAR_WAIT_CLU(sb + OFF_FULL(s), ph);
#pragma unroll
                for (int ks = 0; ks < 4; ks++)
                    MMA_TF32_CG2(tmem, dX[s] + 2 * ks, dH0[s] + 2 * ks, 1u);
                if (p == 15) TC_COMMIT_MC_CG2(sb + OFF_EPI0);   // D0 final
#pragma unroll
                for (int ks = 0; ks < 4; ks++)
                    MMA_TF32_CG2(tmem + 256, dX[s] + 2 * ks, dH1[s] + 2 * ks, 1u);
                TC_COMMIT_MC_CG2(sb + OFF_DONE(s));
                if (p == 15) TC_COMMIT_MC_CG2(sb + OFF_EPI1);   // D1 final
                if (s == 3) ph ^= 1;
            }
        }
    } else if (wid == 1 && lid == 0) {
        // ---------------- TMA producer (both ranks) ----------------
        int cs = 0, ph = 0, filled = 0;
        for (int j = 0; j < cnt; j++) {
            int m0 = (c + NPAIR * j) * 256;
            for (int k = 0; k < 16; k++) {
                if (filled >= NSTAGE)
                    MBAR_WAIT(sb + OFF_DONE(cs), ph ^ 1);   // stage drained (mc commit)
                if (rank == 0)
                    MBAR_EXPECT_TX(sb + OFF_FULL(cs), EXPECT_PAIR);
                // X: own 128 rows of the M=256 tile
                TMA3D_CG2(sb + OFF_STG(cs), &mx, k * KC, m0 + rank * 128, 0,
                          sb + OFF_FULL(cs));
                // H: own 128-row halves of BOTH column blocks in one 3D box
                TMA3D_CG2(sb + OFF_STG(cs) + 16384, &mh, k * KC, rank * 128, 0,
                          sb + OFF_FULL(cs));
                filled++;
                if (++cs == NSTAGE) { cs = 0; ph ^= 1; }
            }
        }
    } else if (wid >= 2) {
        // ---------------- epilogue warps (2..7, both ranks) ----------------
        // Per half (256 cols = 8 chunks): sp0=warp4 (8), sp1=warp5 (8),
        // sp2=warps2/6 (4+4), sp3=warps3/7 (4+4).
        int sp = wid & 3;
        int nch = (sp < 2) ? 8 : 4;
        int ch0 = (sp < 2) ? 0 : ((wid >= 6) ? 4 : 0);
        for (int j = 0; j < cnt; j++) {
            size_t row = (size_t)((c + NPAIR * j) * 256 + rank * 128 + sp * 32 + lid);
            float* orow = out + row * N_F;
#pragma unroll
            for (int half = 0; half < 2; half++) {
                MBAR_WAIT(sb + (half ? OFF_EPI1 : OFF_EPI0), j & 1);
                asm volatile("tcgen05.fence::after_thread_sync;" ::: "memory");
                for (int cc = 0; cc < nch; cc++) {
                    int c0 = half * 256 + (ch0 + cc) * 32;
                    uint32_t r[32];
                    asm volatile(
                        "tcgen05.ld.sync.aligned.32x32b.x32.b32 "
                        "{%0, %1, %2, %3, %4, %5, %6, %7, "
                        " %8, %9, %10, %11, %12, %13, %14, %15, "
                        " %16, %17, %18, %19, %20, %21, %22, %23, "
                        " %24, %25, %26, %27, %28, %29, %30, %31}, [%32];"
                        : "=r"(r[0]),  "=r"(r[1]),  "=r"(r[2]),  "=r"(r[3]),
                          "=r"(r[4]),  "=r"(r[5]),  "=r"(r[6]),  "=r"(r[7]),
                          "=r"(r[8]),  "=r"(r[9]),  "=r"(r[10]), "=r"(r[11]),
                          "=r"(r[12]), "=r"(r[13]), "=r"(r[14]), "=r"(r[15]),
                          "=r"(r[16]), "=r"(r[17]), "=r"(r[18]), "=r"(r[19]),
                          "=r"(r[20]), "=r"(r[21]), "=r"(r[22]), "=r"(r[23]),
                          "=r"(r[24]), "=r"(r[25]), "=r"(r[26]), "=r"(r[27]),
                          "=r"(r[28]), "=r"(r[29]), "=r"(r[30]), "=r"(r[31])
                        : "r"(tmem + c0));
                    asm volatile("tcgen05.wait::ld.sync.aligned;" ::: "memory");
                    if (cc == nch - 1) {
                        // this half's D cols read into regs -> release dispatcher
                        asm volatile("tcgen05.fence::before_thread_sync;" ::: "memory");
                        if (lid == 0) {
                            uint32_t dfrb = sb + (half ? OFF_DFREE1 : OFF_DFREE0);
                            if (rank == 0) { MBAR_ARRIVE(dfrb); }
                            else           { MBAR_ARRIVE_CLUSTER0(dfrb); }
                        }
                    }
#pragma unroll
                    for (int q = 0; q < 8; q++) {
                        float4 bv = *reinterpret_cast<const float4*>(bias + c0 + q * 4);
                        float4 v;
                        v.x = __uint_as_float(r[q * 4 + 0]) + bv.x;
                        v.y = __uint_as_float(r[q * 4 + 1]) + bv.y;
                        v.z = __uint_as_float(r[q * 4 + 2]) + bv.z;
                        v.w = __uint_as_float(r[q * 4 + 3]) + bv.w;
                        *reinterpret_cast<float4*>(orow + c0 + q * 4) = v;
                    }
                }
            }
        }
    }

    __syncthreads();
    // Peer may still be MMA-reading our SMEM / arriving on our barriers.
    CLUSTER_SYNC();
    if (wid == 0) {
        asm volatile("tcgen05.dealloc.cta_group::2.sync.aligned.b32 %0, %1;"
                     :: "r"(tmem), "r"(512));
    }

#else
    // =================== SIMT fp32 fallback (non-'a' pass) ================
    (void)mx; (void)mh;
    extern __shared__ char smem_raw[];
    float* Xs = reinterpret_cast<float*>(smem_raw);          // [128][33]
    float* Hs = Xs + 128 * 33;                               // [64][33]

    int tid = threadIdx.x;
    int ty = tid >> 4, tx = tid & 15;

    for (int g = bid; g < ntiles; g += GRID) {
        int m0 = (g >> 1) * 256;
        int nb = g & 1;
        for (int half = 0; half < 2; half++) {
            int m0h = m0 + half * 128;
            for (int nc = 0; nc < 4; nc++) {
                int col0 = nb * 256 + nc * 64;
                float acc[8][4];
#pragma unroll
                for (int i = 0; i < 8; i++)
#pragma unroll
                    for (int j = 0; j < 4; j++) acc[i][j] = 0.f;

                for (int kb = 0; kb < 16; kb++) {
#pragma unroll
                    for (int it = 0; it < 16; it++) {
                        int idx = tid + it * 256;
                        int r = idx >> 5, k = idx & 31;
                        Xs[r * 33 + k] = x[(size_t)(m0h + r) * N_F + kb * 32 + k];
                    }
#pragma unroll
                    for (int it = 0; it < 8; it++) {
                        int idx = tid + it * 256;
                        int r = idx >> 5, k = idx & 31;
                        Hs[r * 33 + k] = g_H[(size_t)(col0 + r) * N_F + kb * 32 + k];
                    }
                    __syncthreads();
#pragma unroll
                    for (int k = 0; k < 32; k++) {
                        float a8[8], b4[4];
#pragma unroll
                        for (int i = 0; i < 8; i++) a8[i] = Xs[(ty * 8 + i) * 33 + k];
#pragma unroll
                        for (int j = 0; j < 4; j++) b4[j] = Hs[(tx * 4 + j) * 33 + k];
#pragma unroll
                        for (int i = 0; i < 8; i++)
#pragma unroll
                            for (int j = 0; j < 4; j++)
                                acc[i][j] = fmaf(a8[i], b4[j], acc[i][j]);
                    }
                    __syncthreads();
                }
#pragma unroll
                for (int i = 0; i < 8; i++)
#pragma unroll
                    for (int j = 0; j < 4; j++) {
                        int col = col0 + tx * 4 + j;
                        out[(size_t)(m0h + ty * 8 + i) * N_F + col] = acc[i][j] + bias[col];
                    }
            }
        }
    }
#endif
}

// ---------------------------------------------------------------------------
// Host launcher
// ---------------------------------------------------------------------------
typedef CUresult (*PFN_encodeTiled)(
    CUtensorMap*, CUtensorMapDataType, cuuint32_t, void*,
    const cuuint64_t*, const cuuint64_t*, const cuuint32_t*, const cuuint32_t*,
    CUtensorMapInterleave, CUtensorMapSwizzle, CUtensorMapL2promotion,
    CUtensorMapFloatOOBfill);

extern "C" void kernel_launch(void* const* d_in, const int* in_sizes, int n_in,
                              void* d_out, int out_size) {
    const float* x    = (const float*)d_in[0];
    const float* A    = (const float*)d_in[1];
    const float* S    = (const float*)d_in[2];
    const float* bias = (const float*)d_in[3];
    float* out = (float*)d_out;

    long Mrows = (long)in_sizes[0] / N_F;   // 131072
    int ntiles = (int)(Mrows / 256) * 2;    // fallback path only

    build_H<<<N_F, N_F>>>(A, S);

    void* hptr = nullptr;
    cudaGetSymbolAddress(&hptr, g_H);

    // Resolve cuTensorMapEncodeTiled via the runtime (no -lcuda needed).
    PFN_encodeTiled enc = nullptr;
    {
        cudaDriverEntryPointQueryResult st;
        cudaGetDriverEntryPointByVersion("cuTensorMapEncodeTiled", (void**)&enc,
                                         12050, cudaEnableDefault, &st);
    }

    CUtensorMap mx{}, mh{};
    if (enc) {
        {
            // X: 3D [k=512][m=131072][1], box {32,128,1}, SW128
            cuuint64_t dims[3]    = {(cuuint64_t)N_F, (cuuint64_t)Mrows, 1};
            cuuint64_t strides[2] = {(cuuint64_t)N_F * 4, (cuuint64_t)N_F * 4 * Mrows};
            cuuint32_t box[3]     = {KC, 128, 1};
            cuuint32_t es[3]      = {1, 1, 1};
            enc(&mx, CU_TENSOR_MAP_DATA_TYPE_FLOAT32, 3, (void*)x,
                dims, strides, box, es,
                CU_TENSOR_MAP_INTERLEAVE_NONE, CU_TENSOR_MAP_SWIZZLE_128B,
                CU_TENSOR_MAP_L2_PROMOTION_L2_128B, CU_TENSOR_MAP_FLOAT_OOB_FILL_NONE);
        }
        {
            // H: 3D [k=512][row-in-block=256][block=2], box {32,128,2}, SW128
            cuuint64_t dims[3]    = {(cuuint64_t)N_F, 256, 2};
            cuuint64_t strides[2] = {(cuuint64_t)N_F * 4, (cuuint64_t)N_F * 4 * 256};
            cuuint32_t box[3]     = {KC, 128, 2};
            cuuint32_t es[3]      = {1, 1, 1};
            enc(&mh, CU_TENSOR_MAP_DATA_TYPE_FLOAT32, 3, hptr,
                dims, strides, box, es,
                CU_TENSOR_MAP_INTERLEAVE_NONE, CU_TENSOR_MAP_SWIZZLE_128B,
                CU_TENSOR_MAP_L2_PROMOTION_L2_128B, CU_TENSOR_MAP_FLOAT_OOB_FILL_NONE);
        }
    }

    cudaFuncSetAttribute(phm_gemm, cudaFuncAttributeMaxDynamicSharedMemorySize, SMEM_BYTES);
    phm_gemm<<<GRID, 256, SMEM_BYTES>>>(x, bias, out, ntiles, mx, mh);
}

// round 12
// speedup vs baseline: 1.9752x; 1.0004x over previous
#include <cuda_runtime.h>
#include <cuda.h>
#include <cstdint>

// ============================================================================
// PHM8Linear: out[131072,512] = X[131072,512] @ H[512,512]^T + bias
// H[a*64+b][c*64+d] = sum_i A[i,a,c] * S[i,b,d]
// tcgen05 TF32 cta_group::2 SS GEMM, persistent grid=148, cluster (2,1,1).
// Pair {2c,2c+1} jointly computes M=256 x N=512 tiles; 48KB/SM/chunk.
// R12: asymmetric rings — X (DRAM-latency) 6x16KB, H (L2-hot) 4x32KB,
// 230KB in flight. Separate FULL/DONE barrier sets per ring; MMA commit
// arrives on both. Epilogue split per N-half with lookahead-4 D0 burst.
// X raw fp32 (HW tf32 truncate); H pre-rounded RN in build_H.
// ============================================================================

#define N_F    512
#define KC     32          // K elems per chunk = 128 bytes = SW128 row
#define NXS    6           // X ring depth
#define NHS    4           // H ring depth
#define GRID   148
#define NPAIR  74
#define M_TILES 512        // 131072/256

__device__ float g_H[N_F * N_F];   // precomputed H (tf32-rounded fp32 bits)

#if defined(__CUDA_ARCH__) && (defined(__CUDA_ARCH_FEAT_SM103_ALL) || \
    defined(__CUDA_ARCH_FEAT_SM100_ALL) || defined(__CUDA_ARCH_FEAT_SM101_ALL))
#define HAS_TCGEN05 1
#else
#define HAS_TCGEN05 0
#endif

// ---------------- smem layout (dynamic), tcgen05 path ----------------
#define OFF_TPTR    0
#define OFF_XFULL(s) (8 + 8 * (s))       //  8..55
#define OFF_XDONE(s) (64 + 8 * (s))      // 64..111
#define OFF_HFULL(s) (120 + 8 * (s))     // 120..151
#define OFF_HDONE(s) (152 + 8 * (s))     // 152..183
#define OFF_EPI0    184
#define OFF_EPI1    192
#define OFF_DFREE0  200
#define OFF_DFREE1  208
#define OFF_XS(s)   (1024 + (s) * 16384)            // 6 x 16KB X stages
#define OFF_HS(s)   (99328 + (s) * 32768)           // 4 x 32KB H stages (H0|H1)
#define SMEM_BYTES  230400
#define EXPECT_X    32768u   // 16KB x 2 CTAs onto leader's barrier
#define EXPECT_H    65536u   // 32KB x 2 CTAs

// idesc: kind::tf32, D=F32(1<<4), A=TF32(2<<7), B=TF32(2<<10), N=256, M=256
#define IDESC_TF32_CG2 ((1u << 4) | (2u << 7) | (2u << 10) | ((256u / 8u) << 17) | ((256u / 16u) << 24))

// K-major SW128 smem descriptor base: layout=SW128(2), version=1, SBO=64, LBO=1
static __device__ __host__ constexpr uint64_t DESC_BASE_SW128 =
    (uint64_t(2) << 61) | (uint64_t(1) << 46) | (uint64_t(64) << 32) | (uint64_t(1) << 16);

__device__ __forceinline__ uint32_t s2u(const void* p) {
    uint32_t a;
    asm("{ .reg .u64 t; cvta.to.shared.u64 t, %1; cvt.u32.u64 %0, t; }" : "=r"(a) : "l"(p));
    return a;
}

#define MBAR_INIT(addr, cnt) \
    asm volatile("mbarrier.init.shared.b64 [%0], %1;" :: "r"(addr), "r"(cnt) : "memory")

#define MBAR_ARRIVE(addr) \
    asm volatile("mbarrier.arrive.shared.b64 _, [%0];" :: "r"(addr) : "memory")

// Arrive on the same-offset mbarrier in cluster CTA rank 0.
#define MBAR_ARRIVE_CLUSTER0(addr)                                             \
    asm volatile("{\n\t.reg .b32 ra;\n\t"                                      \
        "mapa.shared::cluster.u32 ra, %0, %1;\n\t"                             \
        "mbarrier.arrive.shared::cluster.b64 _, [ra];\n\t}"                    \
        :: "r"(addr), "r"(0) : "memory")

#define MBAR_EXPECT_TX(addr, bytes) \
    asm volatile("mbarrier.arrive.expect_tx.shared.b64 _, [%0], %1;" :: "r"(addr), "r"(bytes) : "memory")

#define MBAR_WAIT_SCOPE(addr, parity, SCOPE) do {                              \
    uint32_t _mb = (addr); uint32_t _ph = (parity); uint32_t _dn;              \
    asm volatile("{\n\t.reg .pred p;\n\t"                                      \
        "mbarrier.try_wait.parity.acquire." SCOPE ".shared::cta.b64 p, [%1], %2;\n\t" \
        "selp.b32 %0, 1, 0, p;\n\t}" : "=r"(_dn) : "r"(_mb), "r"(_ph) : "memory"); \
    while (!_dn) {                                                             \
        asm volatile("{\n\t.reg .pred p;\n\t"                                  \
            "mbarrier.try_wait.parity.acquire." SCOPE ".shared::cta.b64 p, [%1], %2, 0x989680;\n\t" \
            "selp.b32 %0, 1, 0, p;\n\t}" : "=r"(_dn) : "r"(_mb), "r"(_ph) : "memory"); \
    }                                                                          \
} while (0)

#define MBAR_WAIT(addr, parity)     MBAR_WAIT_SCOPE(addr, parity, "cta")
#define MBAR_WAIT_CLU(addr, parity) MBAR_WAIT_SCOPE(addr, parity, "cluster")

// cta_group::2 TMA: both CTAs execute; complete_tx targets leader's barrier
// (bit 24 cleared). Data lands in the ISSUING CTA's smem.
#define TMA3D_CG2(smem, map, cx, cy, cz, mbar)                                 \
    asm volatile("{\n\t.reg .b32 lb;\n\t"                                      \
        "and.b32 lb, %5, 0xFEFFFFFF;\n\t"                                      \
        "cp.async.bulk.tensor.3d.cta_group::2.shared::cluster.global"          \
        ".tile.mbarrier::complete_tx::bytes [%0], [%1, {%2, %3, %4}], [lb];\n\t}" \
        :: "r"(smem), "l"(map), "r"(cx), "r"(cy), "r"(cz), "r"(mbar) : "memory")

// cta_group::2 tf32 MMA (leader issues; A/B split across the CTA pair)
#define MMA_TF32_CG2(dst, adsc, bdsc, en)                                      \
    asm volatile("{\n\t.reg .pred p;\n\tsetp.ne.u32 p, %5, 0;\n\t"             \
        "tcgen05.mma.cta_group::2.kind::tf32 [%0], %1, %2, %3, "               \
        "{%4,%4,%4,%4,%4,%4,%4,%4}, p;\n\t}"                                   \
        :: "r"(dst), "l"(adsc), "l"(bdsc), "r"(IDESC_TF32_CG2), "r"(0u), "r"(en) : "memory")

#define TC_COMMIT_MC_CG2(mbar)                                                 \
    asm volatile("tcgen05.commit.cta_group::2.mbarrier::arrive::one.shared::cluster.multicast::cluster.b64 [%0], %1;" \
        :: "r"(mbar), "h"((uint16_t)3) : "memory")

#define CLUSTER_SYNC() do {                                                    \
    asm volatile("barrier.cluster.arrive.aligned;" ::: "memory");              \
    asm volatile("barrier.cluster.wait.aligned;" ::: "memory");                \
} while (0)

// ---------------------------------------------------------------------------
// H precompute: H[r=a*64+b][k=c*64+d] = sum_i A[i,a,c]*S[i,b,d], RN->tf32
// ---------------------------------------------------------------------------
__global__ void build_H(const float* __restrict__ A, const float* __restrict__ S) {
    int r = blockIdx.x;     // 0..511
    int k = threadIdx.x;    // 0..511
    int a = r >> 6, bb = r & 63, c = k >> 6, d = k & 63;
    float acc = 0.f;
#pragma unroll
    for (int i = 0; i < 8; i++)
        acc = fmaf(A[i * 64 + a * 8 + c], S[i * 4096 + bb * 64 + d], acc);
    uint32_t t;
    asm("cvt.rna.tf32.f32 %0, %1;" : "=r"(t) : "f"(acc));
    g_H[r * N_F + k] = __uint_as_float(t);
}

// ---------------------------------------------------------------------------
// Main GEMM kernel
// ---------------------------------------------------------------------------
__global__ void __launch_bounds__(256, 1) __cluster_dims__(2, 1, 1) phm_gemm(
    const float* __restrict__ x,
    const float* __restrict__ bias, float* __restrict__ out,
    int ntiles,
    const __grid_constant__ CUtensorMap mx,
    const __grid_constant__ CUtensorMap mh)
{
    int bid = blockIdx.x;

#if HAS_TCGEN05
    // =================== tcgen05 TF32 cg2 path (sm_103a) ==================
    (void)x; (void)ntiles;
    extern __shared__ char smem_raw[];
    uint32_t sb = s2u(smem_raw);
    int tid = threadIdx.x, wid = tid >> 5, lid = tid & 31;

    int c    = bid >> 1;        // pair id (0..73)
    int rank = bid & 1;         // cluster rank
    int cnt  = 1 + (M_TILES - 1 - c) / NPAIR;   // tiles for this pair

    if (wid == 0) {
        asm volatile("tcgen05.alloc.cta_group::2.sync.aligned.shared::cta.b32 [%0], %1;"
                     :: "r"(sb + OFF_TPTR), "r"(512) : "memory");
        asm volatile("tcgen05.relinquish_alloc_permit.cta_group::2.sync.aligned;");
    }
    if (tid == 0) {
#pragma unroll
        for (int s = 0; s < NXS; s++) {
            MBAR_INIT(sb + OFF_XFULL(s), 1);
            MBAR_INIT(sb + OFF_XDONE(s), 1);
        }
#pragma unroll
        for (int s = 0; s < NHS; s++) {
            MBAR_INIT(sb + OFF_HFULL(s), 1);
            MBAR_INIT(sb + OFF_HDONE(s), 1);
        }
        MBAR_INIT(sb + OFF_EPI0, 1);
        MBAR_INIT(sb + OFF_EPI1, 1);
        MBAR_INIT(sb + OFF_DFREE0, 12);      // 6 epilogue warps x 2 CTAs
        MBAR_INIT(sb + OFF_DFREE1, 12);
    }
    __syncthreads();
    uint32_t tmem;
    asm volatile("ld.shared.b32 %0, [%1];" : "=r"(tmem) : "r"(sb + OFF_TPTR));

    // All mbarriers live in both CTAs before any cross-CTA TMA/commit.
    CLUSTER_SYNC();

    if (wid == 0 && lid == 0 && rank == 0) {
        // ---------------- MMA dispatcher (leader only) ----------------
        uint64_t dX[NXS], dH0[NHS], dH1[NHS];
#pragma unroll
        for (int s = 0; s < NXS; s++)
            dX[s]  = DESC_BASE_SW128 | (((sb + OFF_XS(s)) >> 4) & 0x3FFF);
#pragma unroll
        for (int s = 0; s < NHS; s++) {
            dH0[s] = DESC_BASE_SW128 | (((sb + OFF_HS(s))         >> 4) & 0x3FFF);
            dH1[s] = DESC_BASE_SW128 | (((sb + OFF_HS(s) + 16384) >> 4) & 0x3FFF);
        }
        int xs = 0, xph = 0, hs = 0, hph = 0;   // full-wait ring cursors
        for (int j = 0; j < cnt; j++) {
            int sx[4], sh[4];
            // ---- phase A: positions 0..3, D0 MMAs (overlap epilogue D1 read)
            if (j > 0) {
                MBAR_WAIT(sb + OFF_DFREE0, (j - 1) & 1);
                asm volatile("tcgen05.fence::after_thread_sync;" ::: "memory");
            }
#pragma unroll
            for (int q = 0; q < 4; q++) {
                MBAR_WAIT_CLU(sb + OFF_XFULL(xs), xph);
                MBAR_WAIT_CLU(sb + OFF_HFULL(hs), hph);
#pragma unroll
                for (int ks = 0; ks < 4; ks++)
                    MMA_TF32_CG2(tmem, dX[xs] + 2 * ks, dH0[hs] + 2 * ks, (q | ks) ? 1u : 0u);
                sx[q] = xs; sh[q] = hs;
                if (++xs == NXS) { xs = 0; xph ^= 1; }
                if (++hs == NHS) { hs = 0; hph ^= 1; }
            }
            // ---- phase B: D1 for positions 0..3 + done commits
            if (j > 0) {
                MBAR_WAIT(sb + OFF_DFREE1, (j - 1) & 1);
                asm volatile("tcgen05.fence::after_thread_sync;" ::: "memory");
            }
#pragma unroll
            for (int q = 0; q < 4; q++) {
#pragma unroll
                for (int ks = 0; ks < 4; ks++)
                    MMA_TF32_CG2(tmem + 256, dX[sx[q]] + 2 * ks, dH1[sh[q]] + 2 * ks, (q | ks) ? 1u : 0u);
                TC_COMMIT_MC_CG2(sb + OFF_XDONE(sx[q]));
                TC_COMMIT_MC_CG2(sb + OFF_HDONE(sh[q]));
            }
            // ---- steady positions 4..15
            for (int p = 4; p < 16; p++) {
                MBAR_WAIT_CLU(sb + OFF_XFULL(xs), xph);
                MBAR_WAIT_CLU(sb + OFF_HFULL(hs), hph);
#pragma unroll
                for (int ks = 0; ks < 4; ks++)
                    MMA_TF32_CG2(tmem, dX[xs] + 2 * ks, dH0[hs] + 2 * ks, 1u);
                if (p == 15) TC_COMMIT_MC_CG2(sb + OFF_EPI0);   // D0 final
#pragma unroll
                for (int ks = 0; ks < 4; ks++)
                    MMA_TF32_CG2(tmem + 256, dX[xs] + 2 * ks, dH1[hs] + 2 * ks, 1u);
                TC_COMMIT_MC_CG2(sb + OFF_XDONE(xs));
                TC_COMMIT_MC_CG2(sb + OFF_HDONE(hs));
                if (p == 15) TC_COMMIT_MC_CG2(sb + OFF_EPI1);   // D1 final
                if (++xs == NXS) { xs = 0; xph ^= 1; }
                if (++hs == NHS) { hs = 0; hph ^= 1; }
            }
        }
    } else if (wid == 1 && lid == 0) {
        // ---------------- TMA producer (both ranks) ----------------
        int xs = 0, xph = 0, hs = 0, hph = 0;
        int filled = 0;
        for (int j = 0; j < cnt; j++) {
            int m0 = (c + NPAIR * j) * 256;
            for (int k = 0; k < 16; k++) {
                // X fill (DRAM stream; deep ring)
                if (filled >= NXS)
                    MBAR_WAIT(sb + OFF_XDONE(xs), xph ^ 1);
                if (rank == 0)
                    MBAR_EXPECT_TX(sb + OFF_XFULL(xs), EXPECT_X);
                TMA3D_CG2(sb + OFF_XS(xs), &mx, k * KC, m0 + rank * 128, 0,
                          sb + OFF_XFULL(xs));
                // H fill (L2-hot; shallow ring); both column-block halves, 3D
                if (filled >= NHS)
                    MBAR_WAIT(sb + OFF_HDONE(hs), hph ^ 1);
                if (rank == 0)
                    MBAR_EXPECT_TX(sb + OFF_HFULL(hs), EXPECT_H);
                TMA3D_CG2(sb + OFF_HS(hs), &mh, k * KC, rank * 128, 0,
                          sb + OFF_HFULL(hs));
                filled++;
                if (++xs == NXS) { xs = 0; xph ^= 1; }
                if (++hs == NHS) { hs = 0; hph ^= 1; }
            }
        }
    } else if (wid >= 2) {
        // ---------------- epilogue warps (2..7, both ranks) ----------------
        // Per half (256 cols = 8 chunks): sp0=warp4 (8), sp1=warp5 (8),
        // sp2=warps2/6 (4+4), sp3=warps3/7 (4+4).
        int sp = wid & 3;
        int nch = (sp < 2) ? 8 : 4;
        int ch0 = (sp < 2) ? 0 : ((wid >= 6) ? 4 : 0);
        for (int j = 0; j < cnt; j++) {
            size_t row = (size_t)((c + NPAIR * j) * 256 + rank * 128 + sp * 32 + lid);
            float* orow = out + row * N_F;
#pragma unroll
            for (int half = 0; half < 2; half++) {
                MBAR_WAIT(sb + (half ? OFF_EPI1 : OFF_EPI0), j & 1);
                asm volatile("tcgen05.fence::after_thread_sync;" ::: "memory");
                for (int cc = 0; cc < nch; cc++) {
                    int c0 = half * 256 + (ch0 + cc) * 32;
                    uint32_t r[32];
                    asm volatile(
                        "tcgen05.ld.sync.aligned.32x32b.x32.b32 "
                        "{%0, %1, %2, %3, %4, %5, %6, %7, "
                        " %8, %9, %10, %11, %12, %13, %14, %15, "
                        " %16, %17, %18, %19, %20, %21, %22, %23, "
                        " %24, %25, %26, %27, %28, %29, %30, %31}, [%32];"
                        : "=r"(r[0]),  "=r"(r[1]),  "=r"(r[2]),  "=r"(r[3]),
                          "=r"(r[4]),  "=r"(r[5]),  "=r"(r[6]),  "=r"(r[7]),
                          "=r"(r[8]),  "=r"(r[9]),  "=r"(r[10]), "=r"(r[11]),
                          "=r"(r[12]), "=r"(r[13]), "=r"(r[14]), "=r"(r[15]),
                          "=r"(r[16]), "=r"(r[17]), "=r"(r[18]), "=r"(r[19]),
                          "=r"(r[20]), "=r"(r[21]), "=r"(r[22]), "=r"(r[23]),
                          "=r"(r[24]), "=r"(r[25]), "=r"(r[26]), "=r"(r[27]),
                          "=r"(r[28]), "=r"(r[29]), "=r"(r[30]), "=r"(r[31])
                        : "r"(tmem + c0));
                    asm volatile("tcgen05.wait::ld.sync.aligned;" ::: "memory");
                    if (cc == nch - 1) {
                        // this half's D cols read into regs -> release dispatcher
                        asm volatile("tcgen05.fence::before_thread_sync;" ::: "memory");
                        if (lid == 0) {
                            uint32_t dfrb = sb + (half ? OFF_DFREE1 : OFF_DFREE0);
                            if (rank == 0) { MBAR_ARRIVE(dfrb); }
                            else           { MBAR_ARRIVE_CLUSTER0(dfrb); }
                        }
                    }
#pragma unroll
                    for (int q = 0; q < 8; q++) {
                        float4 bv = *reinterpret_cast<const float4*>(bias + c0 + q * 4);
                        float4 v;
                        v.x = __uint_as_float(r[q * 4 + 0]) + bv.x;
                        v.y = __uint_as_float(r[q * 4 + 1]) + bv.y;
                        v.z = __uint_as_float(r[q * 4 + 2]) + bv.z;
                        v.w = __uint_as_float(r[q * 4 + 3]) + bv.w;
                        *reinterpret_cast<float4*>(orow + c0 + q * 4) = v;
                    }
                }
            }
        }
    }

    __syncthreads();
    // Peer may still be MMA-reading our SMEM / arriving on our barriers.
    CLUSTER_SYNC();
    if (wid == 0) {
        asm volatile("tcgen05.dealloc.cta_group::2.sync.aligned.b32 %0, %1;"
                     :: "r"(tmem), "r"(512));
    }

#else
    // =================== SIMT fp32 fallback (non-'a' pass) ================
    (void)mx; (void)mh;
    extern __shared__ char smem_raw[];
    float* Xs = reinterpret_cast<float*>(smem_raw);          // [128][33]
    float* Hs = Xs + 128 * 33;                               // [64][33]

    int tid = threadIdx.x;
    int ty = tid >> 4, tx = tid & 15;

    for (int g = bid; g < ntiles; g += GRID) {
        int m0 = (g >> 1) * 256;
        int nb = g & 1;
        for (int half = 0; half < 2; half++) {
            int m0h = m0 + half * 128;
            for (int nc = 0; nc < 4; nc++) {
                int col0 = nb * 256 + nc * 64;
                float acc[8][4];
#pragma unroll
                for (int i = 0; i < 8; i++)
#pragma unroll
                    for (int j = 0; j < 4; j++) acc[i][j] = 0.f;

                for (int kb = 0; kb < 16; kb++) {
#pragma unroll
                    for (int it = 0; it < 16; it++) {
                        int idx = tid + it * 256;
                        int r = idx >> 5, k = idx & 31;
                        Xs[r * 33 + k] = x[(size_t)(m0h + r) * N_F + kb * 32 + k];
                    }
#pragma unroll
                    for (int it = 0; it < 8; it++) {
                        int idx = tid + it * 256;
                        int r = idx >> 5, k = idx & 31;
                        Hs[r * 33 + k] = g_H[(size_t)(col0 + r) * N_F + kb * 32 + k];
                    }
                    __syncthreads();
#pragma unroll
                    for (int k = 0; k < 32; k++) {
                        float a8[8], b4[4];
#pragma unroll
                        for (int i = 0; i < 8; i++) a8[i] = Xs[(ty * 8 + i) * 33 + k];
#pragma unroll
                        for (int j = 0; j < 4; j++) b4[j] = Hs[(tx * 4 + j) * 33 + k];
#pragma unroll
                        for (int i = 0; i < 8; i++)
#pragma unroll
                            for (int j = 0; j < 4; j++)
                                acc[i][j] = fmaf(a8[i], b4[j], acc[i][j]);
                    }
                    __syncthreads();
                }
#pragma unroll
                for (int i = 0; i < 8; i++)
#pragma unroll
                    for (int j = 0; j < 4; j++) {
                        int col = col0 + tx * 4 + j;
                        out[(size_t)(m0h + ty * 8 + i) * N_F + col] = acc[i][j] + bias[col];
                    }
            }
        }
    }
#endif
}

// ---------------------------------------------------------------------------
// Host launcher
// ---------------------------------------------------------------------------
typedef CUresult (*PFN_encodeTiled)(
    CUtensorMap*, CUtensorMapDataType, cuuint32_t, void*,
    const cuuint64_t*, const cuuint64_t*, const cuuint32_t*, const cuuint32_t*,
    CUtensorMapInterleave, CUtensorMapSwizzle, CUtensorMapL2promotion,
    CUtensorMapFloatOOBfill);

extern "C" void kernel_launch(void* const* d_in, const int* in_sizes, int n_in,
                              void* d_out, int out_size) {
    const float* x    = (const float*)d_in[0];
    const float* A    = (const float*)d_in[1];
    const float* S    = (const float*)d_in[2];
    const float* bias = (const float*)d_in[3];
    float* out = (float*)d_out;

    long Mrows = (long)in_sizes[0] / N_F;   // 131072
    int ntiles = (int)(Mrows / 256) * 2;    // fallback path only

    build_H<<<N_F, N_F>>>(A, S);

    void* hptr = nullptr;
    cudaGetSymbolAddress(&hptr, g_H);

    // Resolve cuTensorMapEncodeTiled via the runtime (no -lcuda needed).
    PFN_encodeTiled enc = nullptr;
    {
        cudaDriverEntryPointQueryResult st;
        cudaGetDriverEntryPointByVersion("cuTensorMapEncodeTiled", (void**)&enc,
                                         12050, cudaEnableDefault, &st);
    }

    CUtensorMap mx{}, mh{};
    if (enc) {
        {
            // X: 3D [k=512][m=131072][1], box {32,128,1}, SW128
            cuuint64_t dims[3]    = {(cuuint64_t)N_F, (cuuint64_t)Mrows, 1};
            cuuint64_t strides[2] = {(cuuint64_t)N_F * 4, (cuuint64_t)N_F * 4 * Mrows};
            cuuint32_t box[3]     = {KC, 128, 1};
            cuuint32_t es[3]      = {1, 1, 1};
            enc(&mx, CU_TENSOR_MAP_DATA_TYPE_FLOAT32, 3, (void*)x,
                dims, strides, box, es,
                CU_TENSOR_MAP_INTERLEAVE_NONE, CU_TENSOR_MAP_SWIZZLE_128B,
                CU_TENSOR_MAP_L2_PROMOTION_L2_128B, CU_TENSOR_MAP_FLOAT_OOB_FILL_NONE);
        }
        {
            // H: 3D [k=512][row-in-block=256][block=2], box {32,128,2}, SW128
            cuuint64_t dims[3]    = {(cuuint64_t)N_F, 256, 2};
            cuuint64_t strides[2] = {(cuuint64_t)N_F * 4, (cuuint64_t)N_F * 4 * 256};
            cuuint32_t box[3]     = {KC, 128, 2};
            cuuint32_t es[3]      = {1, 1, 1};
            enc(&mh, CU_TENSOR_MAP_DATA_TYPE_FLOAT32, 3, hptr,
                dims, strides, box, es,
                CU_TENSOR_MAP_INTERLEAVE_NONE, CU_TENSOR_MAP_SWIZZLE_128B,
                CU_TENSOR_MAP_L2_PROMOTION_L2_128B, CU_TENSOR_MAP_FLOAT_OOB_FILL_NONE);
        }
    }

    cudaFuncSetAttribute(phm_gemm, cudaFuncAttributeMaxDynamicSharedMemorySize, SMEM_BYTES);
    phm_gemm<<<GRID, 256, SMEM_BYTES>>>(x, bias, out, ntiles, mx, mh);
}